// round 5
// baseline (speedup 1.0000x reference)
#include <cuda_runtime.h>
#include <math.h>
#include <stdint.h>

// ---------------------------------------------------------------------------
// QuantumHybridCNN, fully fused tf32 version.
//  k_fused: per block of 32 samples: conv1 (scalar) + conv2 (tf32 MMA,
//           warp=sample, no block syncs) -> h2 kept in smem (tf32) ->
//           fc GEMM M=32,N=64,K=1024 (warps split 2xN x 4xK, smem reduce)
//           -> pre(64->4) + tanh -> qin to global.
//  k_tail:  per-sample 4-qubit circuit + post + sigmoid (1 thread/sample).
// ---------------------------------------------------------------------------

#define BMAX 32768
__device__ float g_qin[(size_t)BMAX * 4];

__device__ __forceinline__ float to_tf32(float v) {
    float r; asm("cvt.rna.tf32.f32 %0, %1;" : "=f"(r) : "f"(v)); return r;
}
__device__ __forceinline__ uint32_t fbits(float v) { return __float_as_uint(v); }

__device__ __forceinline__ void mma8(float d[4], const uint32_t a[4],
                                     uint32_t b0, uint32_t b1) {
    asm volatile(
        "mma.sync.aligned.m16n8k8.row.col.f32.tf32.tf32.f32 "
        "{%0,%1,%2,%3}, {%4,%5,%6,%7}, {%8,%9}, {%0,%1,%2,%3};"
        : "+f"(d[0]), "+f"(d[1]), "+f"(d[2]), "+f"(d[3])
        : "r"(a[0]), "r"(a[1]), "r"(a[2]), "r"(a[3]), "r"(b0), "r"(b1));
}

// smem layout (floats)
#define OFF_XS    0                    // [32][64]            = 2048
#define OFF_HS    2048                 // conv: [8 warps][32][40] = 10240
                                       // fc:   Bs[64][72]=4608, Hs @+4608 [32][65]=2080
#define OFF_WSB   12288                // [96][72]            = 6912
#define OFF_BS    19200                // [64]
#define OFF_H2S   19264                // [32][1028]          = 32896 (also P[8][32][33])
#define OFF_CONST 52160                // fcb 64 | prew 256 | preb 4
#define SMEM_FLOATS (OFF_CONST + 324)

__global__ __launch_bounds__(256) void k_fused(
    const float* __restrict__ x,
    const float* __restrict__ c1w, const float* __restrict__ c1b,
    const float* __restrict__ c2w, const float* __restrict__ c2b,
    const float* __restrict__ fcw, const float* __restrict__ fcb,
    const float* __restrict__ prew, const float* __restrict__ preb,
    float* __restrict__ qin_out, int B)
{
    extern __shared__ float sm[];
    float* xs     = sm + OFF_XS;
    float* hs     = sm + OFF_HS;
    float* wsB    = sm + OFF_WSB;
    float* bsv    = sm + OFF_BS;
    float* h2s    = sm + OFF_H2S;
    float* s_fcb  = sm + OFF_CONST;
    float* s_prew = sm + OFF_CONST + 64;
    float* s_preb = sm + OFF_CONST + 320;

    int tid = threadIdx.x;
    int lane = tid & 31, warp = tid >> 5;
    int gid = lane >> 2, tid4 = lane & 3;
    int b0 = blockIdx.x * 32;

    // ---- stage input, conv2 weights (tf32, k = t*32+c), biases, fc consts ----
    for (int i = tid; i < 2048; i += 256) {
        int gidx = b0 * 64 + i;
        xs[i] = (gidx < B * 64) ? x[gidx] : 0.0f;
    }
    for (int i = tid; i < 6144; i += 256) {
        int k = i >> 6, o = i & 63;
        int t = k >> 5, c = k & 31;
        wsB[k * 72 + o] = to_tf32(c2w[o * 96 + c * 3 + t]);
    }
    if (tid < 64) { bsv[tid] = c2b[tid]; s_fcb[tid] = fcb[tid]; }
    s_prew[tid] = prew[tid];
    if (tid < 4) s_preb[tid] = preb[tid];
    __syncthreads();

    // =====================================================================
    // Conv phase: warp = sample, 4 samples per warp, warp-private hs rows.
    // =====================================================================
    float cw0 = __ldg(&c1w[lane * 3 + 0]);
    float cw1 = __ldg(&c1w[lane * 3 + 1]);
    float cw2 = __ldg(&c1w[lane * 3 + 2]);
    float cbb = __ldg(&c1b[lane]);
    float* hw = hs + warp * 1280;           // [32][40]

    for (int g = 0; g < 4; g++) {
        int sb = g * 8 + warp;              // sample within block

        // ---- conv1 + relu + pool (fp32 -> tf32), lane = channel ----
        {
            const float* xr = &xs[sb * 64];
            float* hrow = &hw[lane * 40];
            hrow[0] = 0.0f; hrow[33] = 0.0f;
            #pragma unroll
            for (int j = 0; j < 32; j++) {
                int p = 2 * j;
                float xm = (p == 0)  ? 0.0f : xr[p - 1];
                float xp = (p == 62) ? 0.0f : xr[p + 2];
                float y0 = fmaf(cw0, xm,    fmaf(cw1, xr[p],     fmaf(cw2, xr[p + 1], cbb)));
                float y1 = fmaf(cw0, xr[p], fmaf(cw1, xr[p + 1], fmaf(cw2, xp,        cbb)));
                hrow[j + 1] = to_tf32(fmaxf(fmaxf(y0, y1), 0.0f));
            }
        }
        __syncwarp();

        // ---- conv2 tf32 MMA: M=32 pos, N=64 ch, K=96 (k = t*32+c) ----
        float acc[2][8][4];
        #pragma unroll
        for (int mt = 0; mt < 2; mt++)
            #pragma unroll
            for (int nb = 0; nb < 8; nb++)
                #pragma unroll
                for (int q = 0; q < 4; q++) acc[mt][nb][q] = 0.0f;

        #pragma unroll
        for (int ks = 0; ks < 12; ks++) {
            int k0 = ks * 8;
            int t  = k0 >> 5;
            int c0 = (k0 & 31) + tid4;
            uint32_t a[2][4];
            #pragma unroll
            for (int mt = 0; mt < 2; mt++) {
                int p = mt * 16 + gid + t;
                a[mt][0] = fbits(hw[c0 * 40 + p]);
                a[mt][1] = fbits(hw[c0 * 40 + p + 8]);
                a[mt][2] = fbits(hw[(c0 + 4) * 40 + p]);
                a[mt][3] = fbits(hw[(c0 + 4) * 40 + p + 8]);
            }
            #pragma unroll
            for (int nb = 0; nb < 8; nb++) {
                uint32_t bb0 = fbits(wsB[(k0 + tid4) * 72 + nb * 8 + gid]);
                uint32_t bb1 = fbits(wsB[(k0 + tid4 + 4) * 72 + nb * 8 + gid]);
                mma8(acc[0][nb], a[0], bb0, bb1);
                mma8(acc[1][nb], a[1], bb0, bb1);
            }
        }

        // ---- bias + relu + pool via shfl + tf32 store to h2s[sb][j*64+o] ----
        float* dst = &h2s[sb * 1028];
        #pragma unroll
        for (int mt = 0; mt < 2; mt++) {
            #pragma unroll
            for (int nb = 0; nb < 8; nb++) {
                int cb = nb * 8 + 2 * tid4;
                float bb0 = bsv[cb], bb1 = bsv[cb + 1];
                float v0 = fmaxf(acc[mt][nb][0] + bb0, 0.0f);
                float v1 = fmaxf(acc[mt][nb][1] + bb1, 0.0f);
                float v2 = fmaxf(acc[mt][nb][2] + bb0, 0.0f);
                float v3 = fmaxf(acc[mt][nb][3] + bb1, 0.0f);
                float q0 = __shfl_xor_sync(0xffffffffu, v0, 4);
                float q1 = __shfl_xor_sync(0xffffffffu, v1, 4);
                float q2 = __shfl_xor_sync(0xffffffffu, v2, 4);
                float q3 = __shfl_xor_sync(0xffffffffu, v3, 4);
                if (!(gid & 1)) {
                    int j0 = mt * 8 + (gid >> 1);
                    int j1 = j0 + 4;
                    *(float2*)&dst[j0 * 64 + cb] =
                        make_float2(to_tf32(fmaxf(v0, q0)), to_tf32(fmaxf(v1, q1)));
                    *(float2*)&dst[j1 * 64 + cb] =
                        make_float2(to_tf32(fmaxf(v2, q2)), to_tf32(fmaxf(v3, q3)));
                }
            }
        }
        __syncwarp();
    }
    __syncthreads();   // h2s complete; hs region free

    // =====================================================================
    // fc GEMM: M=32, N=64, K=1024. warp = (wn: N-half, wk: K-slice of 16/chunk)
    // Bs double-buffered through registers. h2 col k' = j*64+o; fcw row = o*16+j.
    // =====================================================================
    int wn = warp >> 2, wk = warp & 3;
    float* Bs = sm + OFF_HS;               // [64][72]

    float facc[2][4][4];
    #pragma unroll
    for (int mt = 0; mt < 2; mt++)
        #pragma unroll
        for (int nb = 0; nb < 4; nb++)
            #pragma unroll
            for (int q = 0; q < 4; q++) facc[mt][nb][q] = 0.0f;

    int kr = tid >> 2, cq = (tid & 3) * 16;
    float4 pre[4];
    {
        int kp = kr;
        int orig = ((kp & 63) << 4) + (kp >> 6);
        const float4* s4 = (const float4*)&fcw[orig * 64 + cq];
        #pragma unroll
        for (int q = 0; q < 4; q++) pre[q] = s4[q];
    }

    for (int chunk = 0; chunk < 16; chunk++) {
        __syncthreads();                   // prior Bs consumers done
        float* d = &Bs[kr * 72 + cq];
        #pragma unroll
        for (int q = 0; q < 4; q++) {
            d[q * 4 + 0] = to_tf32(pre[q].x);
            d[q * 4 + 1] = to_tf32(pre[q].y);
            d[q * 4 + 2] = to_tf32(pre[q].z);
            d[q * 4 + 3] = to_tf32(pre[q].w);
        }
        __syncthreads();
        if (chunk < 15) {                  // prefetch next chunk under MMAs
            int kp = (chunk + 1) * 64 + kr;
            int orig = ((kp & 63) << 4) + (kp >> 6);
            const float4* s4 = (const float4*)&fcw[orig * 64 + cq];
            #pragma unroll
            for (int q = 0; q < 4; q++) pre[q] = s4[q];
        }

        #pragma unroll
        for (int ks = 0; ks < 2; ks++) {
            int kb = wk * 16 + ks * 8 + tid4;     // k within Bs
            int ka = chunk * 64 + kb;             // k within h2s
            uint32_t a[2][4];
            #pragma unroll
            for (int mt = 0; mt < 2; mt++) {
                int r = mt * 16 + gid;
                a[mt][0] = fbits(h2s[r * 1028 + ka]);
                a[mt][1] = fbits(h2s[(r + 8) * 1028 + ka]);
                a[mt][2] = fbits(h2s[r * 1028 + ka + 4]);
                a[mt][3] = fbits(h2s[(r + 8) * 1028 + ka + 4]);
            }
            #pragma unroll
            for (int nb = 0; nb < 4; nb++) {
                uint32_t bb0 = fbits(Bs[kb * 72 + wn * 32 + nb * 8 + gid]);
                uint32_t bb1 = fbits(Bs[(kb + 4) * 72 + wn * 32 + nb * 8 + gid]);
                mma8(facc[0][nb], a[0], bb0, bb1);
                mma8(facc[1][nb], a[1], bb0, bb1);
            }
        }
    }
    __syncthreads();   // all MMAs done; h2s free for partials

    // ---- store per-warp partials P[warp][32][33] into h2s region ----
    float* P = &h2s[warp * 1056];
    #pragma unroll
    for (int mt = 0; mt < 2; mt++) {
        #pragma unroll
        for (int nb = 0; nb < 4; nb++) {
            int r = mt * 16 + gid;
            int c = nb * 8 + 2 * tid4;
            P[r * 33 + c]           = facc[mt][nb][0];
            P[r * 33 + c + 1]       = facc[mt][nb][1];
            P[(r + 8) * 33 + c]     = facc[mt][nb][2];
            P[(r + 8) * 33 + c + 1] = facc[mt][nb][3];
        }
    }
    __syncthreads();

    // ---- reduce 4 K-slices + bias + relu -> Hs[32][65] ----
    float* Hs = sm + OFF_HS + 4608;
    #pragma unroll
    for (int q = 0; q < 8; q++) {
        int idx = tid + q * 256;
        int r = idx >> 6, c = idx & 63;
        int base = (c >> 5) * 4224 + r * 33 + (c & 31);   // (c>>5)*4 warps * 1056
        float v = s_fcb[c] + h2s[base] + h2s[base + 1056]
                + h2s[base + 2112] + h2s[base + 3168];
        Hs[r * 65 + c] = fmaxf(v, 0.0f);
    }
    __syncthreads();

    // ---- pre: 64 -> 4, tanh * pi/2 -> qin ----
    if (tid < 128) {
        int s = tid >> 2, wq = tid & 3;
        const float* h = &Hs[s * 65];
        float d = s_preb[wq];
        #pragma unroll 8
        for (int j = 0; j < 64; j++) d = fmaf(h[j], s_prew[j * 4 + wq], d);
        if (b0 + s < B)
            qin_out[(size_t)(b0 + s) * 4 + wq] = tanhf(d) * 1.5707963267948966f;
    }
}

// ---------------------------------------------------------------------------
// Tail kernel: 4-qubit circuit per thread.
// ---------------------------------------------------------------------------
__device__ __forceinline__ void apply_ry(float st[16], float th, int mask)
{
    float s, c;
    sincosf(th * 0.5f, &s, &c);
    #pragma unroll
    for (int i = 0; i < 16; i++) {
        if (!(i & mask)) {
            int j = i | mask;
            float a = st[i], b = st[j];
            st[i] = c * a - s * b;
            st[j] = s * a + c * b;
        }
    }
}
__device__ __forceinline__ void apply_cnot(float st[16], int cm, int tm)
{
    #pragma unroll
    for (int i = 0; i < 16; i++) {
        if ((i & cm) && !(i & tm)) {
            int j = i | tm;
            float t = st[i]; st[i] = st[j]; st[j] = t;
        }
    }
}

__global__ __launch_bounds__(256) void k_tail(
    const float* __restrict__ qin, const float* __restrict__ qp,
    const float* __restrict__ postw, const float* __restrict__ postb,
    float* __restrict__ out, int B)
{
    __shared__ float s_qp[24], s_pw[4], s_pb[1];
    int tid = threadIdx.x;
    if (tid < 24) s_qp[tid] = qp[tid];
    if (tid < 4)  s_pw[tid] = postw[tid];
    if (tid == 0) s_pb[0]   = postb[0];
    __syncthreads();

    int b = blockIdx.x * 256 + tid;
    if (b >= B) return;

    float4 qv = *(const float4*)&qin[(size_t)b * 4];

    float st[16];
    #pragma unroll
    for (int i = 0; i < 16; i++) st[i] = 0.25f;
    apply_ry(st, qv.x, 8);
    apply_ry(st, qv.y, 4);
    apply_ry(st, qv.z, 2);
    apply_ry(st, qv.w, 1);
    for (int k = 0; k < 6; k++) {
        apply_cnot(st, 8, 4);
        apply_cnot(st, 2, 1);
        apply_cnot(st, 4, 2);
        apply_ry(st, s_qp[4 * k + 0], 8);
        apply_ry(st, s_qp[4 * k + 1], 4);
        apply_ry(st, s_qp[4 * k + 2], 2);
        apply_ry(st, s_qp[4 * k + 3], 1);
    }

    float z0 = 0.f, z1 = 0.f, z2 = 0.f, z3 = 0.f;
    #pragma unroll
    for (int i = 0; i < 16; i++) {
        float p = st[i] * st[i];
        z0 += (i & 8) ? -p : p;
        z1 += (i & 4) ? -p : p;
        z2 += (i & 2) ? -p : p;
        z3 += (i & 1) ? -p : p;
    }

    float t = s_pb[0];
    t = fmaf(z0, s_pw[0], t);
    t = fmaf(z1, s_pw[1], t);
    t = fmaf(z2, s_pw[2], t);
    t = fmaf(z3, s_pw[3], t);
    out[b] = 1.0f / (1.0f + expf(-t));
}

// ---------------------------------------------------------------------------
extern "C" void kernel_launch(void* const* d_in, const int* in_sizes, int n_in,
                              void* d_out, int out_size)
{
    const float* x       = (const float*)d_in[0];
    const float* conv1_w = (const float*)d_in[1];
    const float* conv1_b = (const float*)d_in[2];
    const float* conv2_w = (const float*)d_in[3];
    const float* conv2_b = (const float*)d_in[4];
    const float* fc_w    = (const float*)d_in[5];
    const float* fc_b    = (const float*)d_in[6];
    const float* pre_w   = (const float*)d_in[7];
    const float* pre_b   = (const float*)d_in[8];
    const float* q_par   = (const float*)d_in[9];
    const float* post_w  = (const float*)d_in[10];
    const float* post_b  = (const float*)d_in[11];
    float* out = (float*)d_out;

    int B = in_sizes[0] / 64;
    if (B > BMAX) B = BMAX;

    float* qin;
    cudaGetSymbolAddress((void**)&qin, g_qin);

    size_t smbytes = SMEM_FLOATS * sizeof(float);
    cudaFuncSetAttribute(k_fused, cudaFuncAttributeMaxDynamicSharedMemorySize,
                         (int)smbytes);

    k_fused<<<(B + 31) / 32, 256, smbytes>>>(x, conv1_w, conv1_b, conv2_w,
                                             conv2_b, fc_w, fc_b, pre_w, pre_b,
                                             qin, B);
    k_tail<<<(B + 255) / 256, 256>>>(qin, q_par, post_w, post_b, out, B);
}

// round 6
// speedup vs baseline: 1.2681x; 1.2681x over previous
#include <cuda_runtime.h>
#include <cuda_bf16.h>
#include <math.h>
#include <stdint.h>

// ---------------------------------------------------------------------------
// QuantumHybridCNN, bf16 m16n8k16 tensor-core version (split kernels).
//  k_conv:    conv1 (fp32 scalar, bf16x2-packed out) + conv2 implicit GEMM
//             via mma.m16n8k16.bf16. warp = sample, 8 samples/block.
//  k_fc:      fc GEMM 64 samples/block, M=64 N=64 K=1024 bf16 MMA,
//             + pre(64->4) + tanh -> qin.
//  k_tail:    per-sample 4-qubit circuit + post + sigmoid.
// h2 stored packed bf16x2: h2p[b][kp], kp = (j*64+o)/2.
// ---------------------------------------------------------------------------

#define BMAX 32768
__device__ uint32_t g_h2p[(size_t)BMAX * 512];
__device__ float    g_qin[(size_t)BMAX * 4];

__device__ __forceinline__ uint32_t packbf(float lo, float hi) {
    __nv_bfloat162 h = __floats2bfloat162_rn(lo, hi);
    return *(uint32_t*)&h;
}

__device__ __forceinline__ void mma16(float d[4], const uint32_t a[4],
                                      uint32_t b0, uint32_t b1) {
    asm volatile(
        "mma.sync.aligned.m16n8k16.row.col.f32.bf16.bf16.f32 "
        "{%0,%1,%2,%3}, {%4,%5,%6,%7}, {%8,%9}, {%0,%1,%2,%3};"
        : "+f"(d[0]), "+f"(d[1]), "+f"(d[2]), "+f"(d[3])
        : "r"(a[0]), "r"(a[1]), "r"(a[2]), "r"(a[3]), "r"(b0), "r"(b1));
}

// ---------------------------------------------------------------------------
// Kernel 1: conv1 + conv2 (bf16 MMA). 8 samples/block, warp = sample.
// smem (4B units): xs 512 | hp 8*16*40 u32 = 5120 | wp 48*72 u32 = 3456 | bs 64
// ---------------------------------------------------------------------------
#define CONV_SMEM_U32 (512 + 5120 + 3456 + 64)

__global__ void __launch_bounds__(256, 3) k_conv(
    const float* __restrict__ x,
    const float* __restrict__ c1w, const float* __restrict__ c1b,
    const float* __restrict__ c2w, const float* __restrict__ c2b,
    uint32_t* __restrict__ h2p, int B)
{
    extern __shared__ float sm[];
    float*    xs = sm;                           // [8][64]
    uint32_t* hp = (uint32_t*)(sm + 512);        // [8 warps][16 cp][40]
    uint32_t* wp = (uint32_t*)(sm + 5632);       // [48 kp][72]
    float*    bs = sm + 9088;                    // [64]

    int tid = threadIdx.x;
    int lane = tid & 31, warp = tid >> 5;
    int gid = lane >> 2, tid4 = lane & 3;
    int b0 = blockIdx.x * 8;

    for (int i = tid; i < 512; i += 256) xs[i] = x[b0 * 64 + i];
    // conv2 weights, k = t*32+c, packed over channel pairs (c even, c+1)
    for (int i = tid; i < 3072; i += 256) {
        int kp = i >> 6, o = i & 63;
        int k = 2 * kp, t = k >> 5, c = k & 31;
        wp[kp * 72 + o] = packbf(c2w[o * 96 + c * 3 + t],
                                 c2w[o * 96 + (c + 1) * 3 + t]);
    }
    if (tid < 64) bs[tid] = c2b[tid];
    __syncthreads();

    // ---- conv1 + relu + pool, lane = channel; pack pairs via shfl ----
    {
        float cw0 = __ldg(&c1w[lane * 3 + 0]);
        float cw1 = __ldg(&c1w[lane * 3 + 1]);
        float cw2 = __ldg(&c1w[lane * 3 + 2]);
        float cbb = __ldg(&c1b[lane]);
        const float* xr = &xs[warp * 64];
        uint32_t* hw = hp + warp * 640;
        if (!(lane & 1)) {                       // zero padding cols 0, 33
            hw[(lane >> 1) * 40 + 0]  = 0u;
            hw[(lane >> 1) * 40 + 33] = 0u;
        }
        #pragma unroll
        for (int j = 0; j < 32; j++) {
            int p = 2 * j;
            float xm = (p == 0)  ? 0.0f : xr[p - 1];
            float xp = (p == 62) ? 0.0f : xr[p + 2];
            float y0 = fmaf(cw0, xm,    fmaf(cw1, xr[p],     fmaf(cw2, xr[p + 1], cbb)));
            float y1 = fmaf(cw0, xr[p], fmaf(cw1, xr[p + 1], fmaf(cw2, xp,        cbb)));
            float v = fmaxf(fmaxf(y0, y1), 0.0f);
            float pv = __shfl_xor_sync(0xffffffffu, v, 1);
            if (!(lane & 1)) hw[(lane >> 1) * 40 + j + 1] = packbf(v, pv);
        }
    }
    __syncwarp();

    // ---- conv2 MMA: M=32 pos, N=64 ch, K=96 (6 k16 steps) ----
    const uint32_t* hw = hp + warp * 640;
    float acc[2][8][4];
    #pragma unroll
    for (int mt = 0; mt < 2; mt++)
        #pragma unroll
        for (int nb = 0; nb < 8; nb++)
            #pragma unroll
            for (int q = 0; q < 4; q++) acc[mt][nb][q] = 0.0f;

    #pragma unroll
    for (int ks = 0; ks < 6; ks++) {
        int k0 = ks * 16;
        int t = k0 >> 5, cp0 = (k0 & 31) >> 1, kp0 = k0 >> 1;
        uint32_t a[2][4];
        #pragma unroll
        for (int mt = 0; mt < 2; mt++) {
            int col = mt * 16 + gid + t;         // position + t
            a[mt][0] = hw[(cp0 + tid4) * 40 + col];
            a[mt][1] = hw[(cp0 + tid4) * 40 + col + 8];
            a[mt][2] = hw[(cp0 + tid4 + 4) * 40 + col];
            a[mt][3] = hw[(cp0 + tid4 + 4) * 40 + col + 8];
        }
        #pragma unroll
        for (int nb = 0; nb < 8; nb++) {
            uint32_t bb0 = wp[(kp0 + tid4) * 72 + nb * 8 + gid];
            uint32_t bb1 = wp[(kp0 + tid4 + 4) * 72 + nb * 8 + gid];
            mma16(acc[0][nb], a[0], bb0, bb1);
            mma16(acc[1][nb], a[1], bb0, bb1);
        }
    }

    // ---- bias + relu + pool (shfl_xor 4) + pack bf16x2 -> h2p ----
    uint32_t* dst = &h2p[(size_t)(b0 + warp) * 512];
    #pragma unroll
    for (int mt = 0; mt < 2; mt++) {
        #pragma unroll
        for (int nb = 0; nb < 8; nb++) {
            int cb = nb * 8 + 2 * tid4;
            float bb0 = bs[cb], bb1 = bs[cb + 1];
            float v0 = fmaxf(acc[mt][nb][0] + bb0, 0.0f);
            float v1 = fmaxf(acc[mt][nb][1] + bb1, 0.0f);
            float v2 = fmaxf(acc[mt][nb][2] + bb0, 0.0f);
            float v3 = fmaxf(acc[mt][nb][3] + bb1, 0.0f);
            float q0 = __shfl_xor_sync(0xffffffffu, v0, 4);
            float q1 = __shfl_xor_sync(0xffffffffu, v1, 4);
            float q2 = __shfl_xor_sync(0xffffffffu, v2, 4);
            float q3 = __shfl_xor_sync(0xffffffffu, v3, 4);
            if (!(gid & 1)) {
                int j0 = mt * 8 + (gid >> 1);
                int j1 = j0 + 4;
                dst[(j0 * 64 + cb) >> 1] = packbf(fmaxf(v0, q0), fmaxf(v1, q1));
                dst[(j1 * 64 + cb) >> 1] = packbf(fmaxf(v2, q2), fmaxf(v3, q3));
            }
        }
    }
}

// ---------------------------------------------------------------------------
// Kernel 2: fc GEMM M=64, N=64, K=1024 (bf16 MMA) + pre + tanh.
// 64 samples/block, grid 512. warp = (wm 0..3: m16, wn 0..1: n32).
// smem (4B): As 64*36 u32 | Bs 32*72 u32 | Hs 64*65 f32 | prew 256 | fcb 64 | preb 4
// ---------------------------------------------------------------------------
#define FC_OFF_AS 0
#define FC_OFF_BS (64 * 36)
#define FC_OFF_HS (FC_OFF_BS + 32 * 72)
#define FC_OFF_PW (FC_OFF_HS + 64 * 65)
#define FC_OFF_FB (FC_OFF_PW + 256)
#define FC_OFF_PB (FC_OFF_FB + 64)
#define FC_SMEM_U32 (FC_OFF_PB + 4)

__global__ void __launch_bounds__(256, 4) k_fc(
    const uint32_t* __restrict__ h2p, const float* __restrict__ fcw,
    const float* __restrict__ fcb, const float* __restrict__ prew,
    const float* __restrict__ preb, float* __restrict__ qin_out, int B)
{
    extern __shared__ float sm[];
    uint32_t* As   = (uint32_t*)sm + FC_OFF_AS;   // [64][36]
    uint32_t* Bs   = (uint32_t*)sm + FC_OFF_BS;   // [32 kp][72]
    float* Hs      = sm + FC_OFF_HS;              // [64][65]
    float* s_prew  = sm + FC_OFF_PW;
    float* s_fcb   = sm + FC_OFF_FB;
    float* s_preb  = sm + FC_OFF_PB;

    int tid = threadIdx.x;
    int lane = tid & 31, warp = tid >> 5;
    int gid = lane >> 2, tid4 = lane & 3;
    int wm = warp & 3, wn = warp >> 2;
    int b0 = blockIdx.x * 64;

    s_prew[tid] = prew[tid];
    if (tid < 64) s_fcb[tid] = fcb[tid];
    if (tid < 4)  s_preb[tid] = preb[tid];

    float acc[4][4];
    #pragma unroll
    for (int nb = 0; nb < 4; nb++)
        #pragma unroll
        for (int q = 0; q < 4; q++) acc[nb][q] = 0.0f;

    // staging indices
    int a_r = tid >> 2, a_p = (tid & 3) * 8;          // A: row, kp offset
    int b_kp = tid >> 3, b_c = (tid & 7) * 8;          // B: kp row, col group
    const uint4* a_src = (const uint4*)&h2p[(size_t)(b0 + a_r) * 512 + a_p];

    uint4  pa0, pa1;
    float4 pb0, pb1, pb2, pb3;
    {   // prefetch chunk 0
        pa0 = a_src[0]; pa1 = a_src[1];
        int kpg = b_kp, k2 = 2 * kpg;
        int j = k2 >> 6, o = k2 & 63;
        const float4* r0 = (const float4*)&fcw[(o * 16 + j) * 64 + b_c];
        const float4* r1 = (const float4*)&fcw[((o + 1) * 16 + j) * 64 + b_c];
        pb0 = r0[0]; pb1 = r0[1]; pb2 = r1[0]; pb3 = r1[1];
    }

    for (int ch = 0; ch < 16; ch++) {
        __syncthreads();
        {   // store staged A
            uint32_t* d = &As[a_r * 36 + a_p];
            *(uint4*)d = pa0; *(uint4*)(d + 4) = pa1;
        }
        {   // pack + store staged B
            uint32_t* d = &Bs[b_kp * 72 + b_c];
            d[0] = packbf(pb0.x, pb2.x); d[1] = packbf(pb0.y, pb2.y);
            d[2] = packbf(pb0.z, pb2.z); d[3] = packbf(pb0.w, pb2.w);
            d[4] = packbf(pb1.x, pb3.x); d[5] = packbf(pb1.y, pb3.y);
            d[6] = packbf(pb1.z, pb3.z); d[7] = packbf(pb1.w, pb3.w);
        }
        __syncthreads();
        if (ch < 15) {   // prefetch next chunk
            pa0 = a_src[(ch + 1) * 8];       // 32 u32 = 8 uint4 per chunk row
            pa1 = a_src[(ch + 1) * 8 + 1];
            int kpg = (ch + 1) * 32 + b_kp, k2 = 2 * kpg;
            int j = k2 >> 6, o = k2 & 63;
            const float4* r0 = (const float4*)&fcw[(o * 16 + j) * 64 + b_c];
            const float4* r1 = (const float4*)&fcw[((o + 1) * 16 + j) * 64 + b_c];
            pb0 = r0[0]; pb1 = r0[1]; pb2 = r1[0]; pb3 = r1[1];
        }

        #pragma unroll
        for (int ks = 0; ks < 4; ks++) {
            int kp0 = ks * 8;
            int r = wm * 16 + gid;
            uint32_t a[4];
            a[0] = As[r * 36 + kp0 + tid4];
            a[1] = As[(r + 8) * 36 + kp0 + tid4];
            a[2] = As[r * 36 + kp0 + tid4 + 4];
            a[3] = As[(r + 8) * 36 + kp0 + tid4 + 4];
            #pragma unroll
            for (int nb = 0; nb < 4; nb++) {
                uint32_t bb0 = Bs[(kp0 + tid4) * 72 + wn * 32 + nb * 8 + gid];
                uint32_t bb1 = Bs[(kp0 + tid4 + 4) * 72 + wn * 32 + nb * 8 + gid];
                mma16(acc[nb], a, bb0, bb1);
            }
        }
    }
    __syncthreads();

    // ---- bias + relu -> Hs ----
    #pragma unroll
    for (int nb = 0; nb < 4; nb++) {
        int r = wm * 16 + gid;
        int cb = wn * 32 + nb * 8 + 2 * tid4;
        float bb0 = s_fcb[cb], bb1 = s_fcb[cb + 1];
        Hs[r * 65 + cb]           = fmaxf(acc[nb][0] + bb0, 0.0f);
        Hs[r * 65 + cb + 1]       = fmaxf(acc[nb][1] + bb1, 0.0f);
        Hs[(r + 8) * 65 + cb]     = fmaxf(acc[nb][2] + bb0, 0.0f);
        Hs[(r + 8) * 65 + cb + 1] = fmaxf(acc[nb][3] + bb1, 0.0f);
    }
    __syncthreads();

    // ---- pre: 64 -> 4, tanh * pi/2 ----
    {
        int s = tid >> 2, wq = tid & 3;
        const float* h = &Hs[s * 65];
        float d = s_preb[wq];
        #pragma unroll 8
        for (int j = 0; j < 64; j++) d = fmaf(h[j], s_prew[j * 4 + wq], d);
        if (b0 + s < B)
            qin_out[(size_t)(b0 + s) * 4 + wq] = tanhf(d) * 1.5707963267948966f;
    }
}

// ---------------------------------------------------------------------------
// Kernel 3: per-sample 4-qubit circuit + post + sigmoid.
// ---------------------------------------------------------------------------
__device__ __forceinline__ void apply_ry(float st[16], float th, int mask)
{
    float s, c;
    sincosf(th * 0.5f, &s, &c);
    #pragma unroll
    for (int i = 0; i < 16; i++) {
        if (!(i & mask)) {
            int j = i | mask;
            float a = st[i], b = st[j];
            st[i] = c * a - s * b;
            st[j] = s * a + c * b;
        }
    }
}
__device__ __forceinline__ void apply_cnot(float st[16], int cm, int tm)
{
    #pragma unroll
    for (int i = 0; i < 16; i++) {
        if ((i & cm) && !(i & tm)) {
            int j = i | tm;
            float t = st[i]; st[i] = st[j]; st[j] = t;
        }
    }
}

__global__ __launch_bounds__(256) void k_tail(
    const float* __restrict__ qin, const float* __restrict__ qp,
    const float* __restrict__ postw, const float* __restrict__ postb,
    float* __restrict__ out, int B)
{
    __shared__ float s_qp[24], s_pw[4], s_pb[1];
    int tid = threadIdx.x;
    if (tid < 24) s_qp[tid] = qp[tid];
    if (tid < 4)  s_pw[tid] = postw[tid];
    if (tid == 0) s_pb[0]   = postb[0];
    __syncthreads();

    int b = blockIdx.x * 256 + tid;
    if (b >= B) return;

    float4 qv = *(const float4*)&qin[(size_t)b * 4];

    float st[16];
    #pragma unroll
    for (int i = 0; i < 16; i++) st[i] = 0.25f;
    apply_ry(st, qv.x, 8);
    apply_ry(st, qv.y, 4);
    apply_ry(st, qv.z, 2);
    apply_ry(st, qv.w, 1);
    for (int k = 0; k < 6; k++) {
        apply_cnot(st, 8, 4);
        apply_cnot(st, 2, 1);
        apply_cnot(st, 4, 2);
        apply_ry(st, s_qp[4 * k + 0], 8);
        apply_ry(st, s_qp[4 * k + 1], 4);
        apply_ry(st, s_qp[4 * k + 2], 2);
        apply_ry(st, s_qp[4 * k + 3], 1);
    }

    float z0 = 0.f, z1 = 0.f, z2 = 0.f, z3 = 0.f;
    #pragma unroll
    for (int i = 0; i < 16; i++) {
        float p = st[i] * st[i];
        z0 += (i & 8) ? -p : p;
        z1 += (i & 4) ? -p : p;
        z2 += (i & 2) ? -p : p;
        z3 += (i & 1) ? -p : p;
    }

    float t = s_pb[0];
    t = fmaf(z0, s_pw[0], t);
    t = fmaf(z1, s_pw[1], t);
    t = fmaf(z2, s_pw[2], t);
    t = fmaf(z3, s_pw[3], t);
    out[b] = 1.0f / (1.0f + expf(-t));
}

// ---------------------------------------------------------------------------
extern "C" void kernel_launch(void* const* d_in, const int* in_sizes, int n_in,
                              void* d_out, int out_size)
{
    const float* x       = (const float*)d_in[0];
    const float* conv1_w = (const float*)d_in[1];
    const float* conv1_b = (const float*)d_in[2];
    const float* conv2_w = (const float*)d_in[3];
    const float* conv2_b = (const float*)d_in[4];
    const float* fc_w    = (const float*)d_in[5];
    const float* fc_b    = (const float*)d_in[6];
    const float* pre_w   = (const float*)d_in[7];
    const float* pre_b   = (const float*)d_in[8];
    const float* q_par   = (const float*)d_in[9];
    const float* post_w  = (const float*)d_in[10];
    const float* post_b  = (const float*)d_in[11];
    float* out = (float*)d_out;

    int B = in_sizes[0] / 64;
    if (B > BMAX) B = BMAX;

    uint32_t* h2p;
    float* qin;
    cudaGetSymbolAddress((void**)&h2p, g_h2p);
    cudaGetSymbolAddress((void**)&qin, g_qin);

    size_t conv_sm = CONV_SMEM_U32 * 4;
    size_t fc_sm   = FC_SMEM_U32 * 4;
    cudaFuncSetAttribute(k_conv, cudaFuncAttributeMaxDynamicSharedMemorySize,
                         (int)conv_sm);
    cudaFuncSetAttribute(k_fc, cudaFuncAttributeMaxDynamicSharedMemorySize,
                         (int)fc_sm);

    k_conv<<<(B + 7) / 8, 256, conv_sm>>>(x, conv1_w, conv1_b, conv2_w,
                                          conv2_b, h2p, B);
    k_fc<<<(B + 63) / 64, 256, fc_sm>>>(h2p, fc_w, fc_b, pre_w, pre_b, qin, B);
    k_tail<<<(B + 255) / 256, 256>>>(qin, q_par, post_w, post_b, out, B);
}